// round 8
// baseline (speedup 1.0000x reference)
#include <cuda_runtime.h>
#include <cstdint>

// ShadingLayer: out[b,c,h,w] = sum_k L[b,c,k] * H_k(n[b,:,h,w])
// R7: cp.async.bulk (TMA) -> SMEM double-buffered pipeline.
//   - 2048 blocks = 64 batches x 32; each block: 4 stages x 512 float4-groups.
//   - Stage = 3 planes x 8KB bulk-copied into smem, mbarrier expect_tx=24KB.
//   - Loads hold no registers -> bytes-in-flight no longer RF-bound.
//   - Compute reads smem (LDS.128, conflict-free), stores STG.128 streaming.
//
// d_in[0]: recnormalch fp32 (64,3,512,512)
// d_in[1]: fc_light    fp32 (64,27)
// d_out  : fp32 (64,3,512,512)

#define C1f 0.8862269254527580f
#define C2f 1.0233267079464885f
#define C3f 0.2477079561003757f
#define C4f 0.8580855308097834f
#define C5f 0.4290427654048917f

#define HW (512 * 512)

static __device__ __forceinline__ void stcs4(float* p, float4 v) {
    __stcs(reinterpret_cast<float4*>(p), v);
}

static __device__ __forceinline__ uint32_t smem_u32(const void* p) {
    uint32_t a;
    asm("{ .reg .u64 t; cvta.to.shared.u64 t, %1; cvt.u32.u64 %0, t; }"
        : "=r"(a) : "l"(p));
    return a;
}

static __device__ __forceinline__ void mbar_init(uint32_t mbar, uint32_t cnt) {
    asm volatile("mbarrier.init.shared.b64 [%0], %1;" :: "r"(mbar), "r"(cnt)
                 : "memory");
}
static __device__ __forceinline__ void mbar_expect_tx(uint32_t mbar, uint32_t tx) {
    asm volatile("mbarrier.arrive.expect_tx.shared.b64 _, [%0], %1;"
                 :: "r"(mbar), "r"(tx) : "memory");
}
static __device__ __forceinline__ void bulk_g2s(uint32_t dst, const void* src,
                                                uint32_t bytes, uint32_t mbar) {
    asm volatile(
        "cp.async.bulk.shared::cta.global.mbarrier::complete_tx::bytes "
        "[%0], [%1], %2, [%3];"
        :: "r"(dst), "l"(src), "r"(bytes), "r"(mbar) : "memory");
}
static __device__ __forceinline__ void mbar_wait(uint32_t mbar, uint32_t parity) {
    uint32_t done;
    asm volatile(
        "{\n\t.reg .pred p;\n\t"
        "mbarrier.try_wait.parity.acquire.cta.shared::cta.b64 p, [%1], %2;\n\t"
        "selp.b32 %0, 1, 0, p;\n\t}"
        : "=r"(done) : "r"(mbar), "r"(parity) : "memory");
    if (!done) {
        asm volatile(
            "{\n\t.reg .pred P1;\n\t"
            "WL_%=:\n\t"
            "mbarrier.try_wait.parity.acquire.cta.shared::cta.b64 P1, [%0], %1, 0x989680;\n\t"
            "@P1 bra.uni WD_%=;\n\t"
            "bra.uni WL_%=;\n\t"
            "WD_%=:\n\t}"
            :: "r"(mbar), "r"(parity) : "memory");
    }
}

// stage geometry
#define GROUPS_PER_STAGE 512               // float4 groups
#define STAGE_PLANE_BYTES (GROUPS_PER_STAGE * 16)   // 8192
#define STAGE_BYTES (3 * STAGE_PLANE_BYTES)         // 24576
#define STAGES_PER_BLOCK 4

__global__ __launch_bounds__(256)
void shading_kernel(const float* __restrict__ nrm,
                    const float* __restrict__ light,
                    float* __restrict__ out) {
    __shared__ alignas(128) float buf[2][3][GROUPS_PER_STAGE * 4];  // 48 KB
    __shared__ alignas(8) uint64_t mbar_s[2];

    const unsigned bid = blockIdx.x;
    const int b   = bid >> 5;               // batch   (2048/32 = 64)
    const int blk = bid & 31;               // block within batch
    const int tid = threadIdx.x;

    const uint32_t mb0 = smem_u32(&mbar_s[0]);
    const uint32_t mb1 = smem_u32(&mbar_s[1]);
    const uint32_t sbuf0 = smem_u32(&buf[0][0][0]);
    const uint32_t sbuf1 = smem_u32(&buf[1][0][0]);

    if (tid == 0) {
        mbar_init(mb0, 1);
        mbar_init(mb1, 1);
    }
    __syncthreads();

    // gmem base for this block: groups blk*2048 .. blk*2048+2047
    const float* gbase = nrm + (size_t)b * 3 * HW + (size_t)blk * 2048 * 4;
    float*       obase = out + (size_t)b * 3 * HW + (size_t)blk * 2048 * 4;

    // ---- prologue: stages 0 and 1 in flight ----
    if (tid == 0) {
        #pragma unroll
        for (int s = 0; s < 2; s++) {
            const uint32_t mb = s ? mb1 : mb0;
            const uint32_t sb = s ? sbuf1 : sbuf0;
            const float* g = gbase + (size_t)s * GROUPS_PER_STAGE * 4;
            mbar_expect_tx(mb, STAGE_BYTES);
            bulk_g2s(sb,                          g,          STAGE_PLANE_BYTES, mb);
            bulk_g2s(sb + STAGE_PLANE_BYTES,      g + HW,     STAGE_PLANE_BYTES, mb);
            bulk_g2s(sb + 2 * STAGE_PLANE_BYTES,  g + 2 * HW, STAGE_PLANE_BYTES, mb);
        }
    }

    // ---- fold light coefficients (off critical path, under TMA latency) ----
    const float* Lb = light + b * 27;
    float a[3][9];
    #pragma unroll
    for (int c = 0; c < 3; c++) {
        a[c][0] = C1f * __ldg(Lb + 9 * c + 0);
        a[c][1] = C2f * __ldg(Lb + 9 * c + 1);
        a[c][2] = C2f * __ldg(Lb + 9 * c + 2);
        a[c][3] = C2f * __ldg(Lb + 9 * c + 3);
        a[c][4] = C3f * __ldg(Lb + 9 * c + 4);
        a[c][5] = C4f * __ldg(Lb + 9 * c + 5);
        a[c][6] = C4f * __ldg(Lb + 9 * c + 6);
        a[c][7] = C5f * __ldg(Lb + 9 * c + 7);
        a[c][8] = C4f * __ldg(Lb + 9 * c + 8);
    }

    #pragma unroll 1
    for (int s = 0; s < STAGES_PER_BLOCK; s++) {
        const int slot = s & 1;
        const uint32_t parity = (s >> 1) & 1;
        mbar_wait(slot ? mb1 : mb0, parity);

        // compute 2 groups: tid and tid+256 within the stage
        float* q0 = obase + (size_t)s * GROUPS_PER_STAGE * 4 + (size_t)tid * 4;
        #pragma unroll
        for (int g = 0; g < 2; g++) {
            const int grp = tid + g * 256;
            const float4 X = *reinterpret_cast<const float4*>(&buf[slot][0][grp * 4]);
            const float4 Y = *reinterpret_cast<const float4*>(&buf[slot][1][grp * 4]);
            const float4 Z = *reinterpret_cast<const float4*>(&buf[slot][2][grp * 4]);
            const float xs[4] = {X.x, X.y, X.z, X.w};
            const float ys[4] = {Y.x, Y.y, Y.z, Y.w};
            const float zs[4] = {Z.x, Z.y, Z.z, Z.w};
            float o[3][4];
            #pragma unroll
            for (int j = 0; j < 4; j++) {
                const float x = xs[j], y = ys[j], z = zs[j];
                const float xx = x * x;
                const float yy = y * y;
                const float b5 = 2.0f * z * z - xx - yy;
                const float b6 = x * z;
                const float b7 = y * z;
                const float b8 = xx - yy;
                const float b9 = x * y;
                #pragma unroll
                for (int c = 0; c < 3; c++) {
                    float r = a[c][0];
                    r = fmaf(a[c][1], z,  r);
                    r = fmaf(a[c][2], x,  r);
                    r = fmaf(a[c][3], y,  r);
                    r = fmaf(a[c][4], b5, r);
                    r = fmaf(a[c][5], b6, r);
                    r = fmaf(a[c][6], b7, r);
                    r = fmaf(a[c][7], b8, r);
                    r = fmaf(a[c][8], b9, r);
                    o[c][j] = r;
                }
            }
            float* q = q0 + (size_t)g * 256 * 4;
            stcs4(q,          make_float4(o[0][0], o[0][1], o[0][2], o[0][3]));
            stcs4(q + HW,     make_float4(o[1][0], o[1][1], o[1][2], o[1][3]));
            stcs4(q + 2 * HW, make_float4(o[2][0], o[2][1], o[2][2], o[2][3]));
        }

        __syncthreads();   // all threads done with this slot

        // refill this slot with stage s+2
        if (tid == 0 && s + 2 < STAGES_PER_BLOCK) {
            const uint32_t mb = slot ? mb1 : mb0;
            const uint32_t sb = slot ? sbuf1 : sbuf0;
            const float* g = gbase + (size_t)(s + 2) * GROUPS_PER_STAGE * 4;
            mbar_expect_tx(mb, STAGE_BYTES);
            bulk_g2s(sb,                          g,          STAGE_PLANE_BYTES, mb);
            bulk_g2s(sb + STAGE_PLANE_BYTES,      g + HW,     STAGE_PLANE_BYTES, mb);
            bulk_g2s(sb + 2 * STAGE_PLANE_BYTES,  g + 2 * HW, STAGE_PLANE_BYTES, mb);
        }
    }
}

extern "C" void kernel_launch(void* const* d_in, const int* in_sizes, int n_in,
                              void* d_out, int out_size) {
    const float* nrm   = (const float*)d_in[0];
    const float* light = (const float*)d_in[1];
    float* out = (float*)d_out;

    // 64 batches * 32 blocks = 2048 blocks, 256 threads,
    // 4 stages x 512 float4-groups per block
    shading_kernel<<<2048, 256>>>(nrm, light, out);
}